// round 3
// baseline (speedup 1.0000x reference)
#include <cuda_runtime.h>
#include <mma.h>
#include <cmath>

using namespace nvcuda;

#define T_TOK 4096
#define NE    8
#define HDIM  2048
#define IDIM  4096
#define TOPK  2
#define NSLOT (T_TOK * TOPK)

#define TM   128
#define TN   64
#define KC   16
#define PADX 24   // sX row stride (floats); 96B, multiple of 16B
#define PADW 72   // sW row stride (floats); 288B, multiple of 16B
#define PADS 20   // staging row stride; 80B, multiple of 16B

// ---------------- scratch (static device memory; no allocations) ----------------
__device__ float g_act[(size_t)NSLOT * IDIM];   // 128 MB activation scratch
__device__ int   g_counts[NE];
__device__ int   g_pos[NE];
__device__ int   g_off[NE + 1];
__device__ int   g_tok_e[T_TOK * TOPK];
__device__ float g_tok_w[T_TOK * TOPK];
__device__ int   g_slot_tok[NSLOT];
__device__ float g_slot_w[NSLOT];

// ---------------- init: zero output + counters ----------------
__global__ void k_init(float* __restrict__ out, int n) {
    int i = blockIdx.x * blockDim.x + threadIdx.x;
    if (i < n) out[i] = 0.f;
    if (i < NE) { g_counts[i] = 0; g_pos[i] = 0; }
}

// ---------------- routing: softmax -> top2 -> renormalize ----------------
__global__ void k_route(const float* __restrict__ logits) {
    int t = blockIdx.x * blockDim.x + threadIdx.x;
    if (t >= T_TOK) return;
    float p[NE];
    float mx = -1e30f;
#pragma unroll
    for (int e = 0; e < NE; e++) { p[e] = logits[t * NE + e]; mx = fmaxf(mx, p[e]); }
#pragma unroll
    for (int e = 0; e < NE; e++) p[e] = expf(p[e] - mx);
    // top-2 (lowest index wins ties, matching jax.lax.top_k)
    int i0 = 0;
#pragma unroll
    for (int e = 1; e < NE; e++) if (p[e] > p[i0]) i0 = e;
    int i1 = (i0 == 0) ? 1 : 0;
#pragma unroll
    for (int e = 0; e < NE; e++) if (e != i0 && p[e] > p[i1]) i1 = e;
    float w0 = p[i0], w1 = p[i1];
    float s = w0 + w1;
    w0 /= s; w1 /= s;
    g_tok_e[t * 2]     = i0;  g_tok_e[t * 2 + 1] = i1;
    g_tok_w[t * 2]     = w0;  g_tok_w[t * 2 + 1] = w1;
    atomicAdd(&g_counts[i0], 1);
    atomicAdd(&g_counts[i1], 1);
}

__global__ void k_scan() {
    int acc = 0;
    for (int e = 0; e < NE; e++) { g_off[e] = acc; acc += g_counts[e]; }
    g_off[NE] = acc;
}

__global__ void k_scatter() {
    int t = blockIdx.x * blockDim.x + threadIdx.x;
    if (t >= T_TOK) return;
#pragma unroll
    for (int j = 0; j < TOPK; j++) {
        int e = g_tok_e[t * 2 + j];
        int pos = atomicAdd(&g_pos[e], 1);
        int s = g_off[e] + pos;
        g_slot_tok[s] = t;
        g_slot_w[s]   = g_tok_w[t * 2 + j];
    }
}

// ---------------- GEMM1: A[slot, 0:I] = silu(Xg @ W1) * (Xg @ W3) ----------------
// grid: (I/TN=64, 32 m-tiles max, E) block: 256 threads (8 warps = 4x2)
__global__ __launch_bounds__(256) void k_gemm1(const float* __restrict__ X,
                                               const float* __restrict__ W13) {
    int e = blockIdx.z;
    int m_beg = g_off[e], m_end = g_off[e + 1];
    int m0 = m_beg + blockIdx.y * TM;
    if (m0 >= m_end) return;
    int n0 = blockIdx.x * TN;   // column within [0, I)

    __shared__ float sX[TM][PADX];
    __shared__ float sW1[KC][PADW];
    __shared__ float sW3[KC][PADW];
    __shared__ float stag[8][16][PADS];
    __shared__ int   stok[TM];

    int tid = threadIdx.x, warp = tid >> 5, lane = tid & 31;
    int wm = warp >> 1;  // 0..3
    int wn = warp & 1;   // 0..1

    if (tid < TM) {
        int gr = m0 + tid;
        stok[tid] = (gr < m_end) ? g_slot_tok[gr] : -1;
    }
    __syncthreads();

    wmma::fragment<wmma::accumulator, 16, 16, 8, float> accg[2][2], accu[2][2];
#pragma unroll
    for (int i = 0; i < 2; i++)
#pragma unroll
        for (int j = 0; j < 2; j++) {
            wmma::fill_fragment(accg[i][j], 0.f);
            wmma::fill_fragment(accu[i][j], 0.f);
        }

    const float* Wbase = W13 + (size_t)e * HDIM * (2 * IDIM);

    for (int k0 = 0; k0 < HDIM; k0 += KC) {
        // X tile: 128 rows x 16 cols -> 512 float4, 2 per thread
#pragma unroll
        for (int it = 0; it < 2; it++) {
            int f = tid + it * 256;
            int r = f >> 2, seg = f & 3;
            int tok = stok[r];
            float4 v = make_float4(0.f, 0.f, 0.f, 0.f);
            if (tok >= 0) v = *(const float4*)&X[(size_t)tok * HDIM + k0 + seg * 4];
            *(float4*)&sX[r][seg * 4] = v;
        }
        // W1/W3 tiles: 16 x 64 each -> 256 float4 each, 1 each per thread
        {
            int r = tid >> 4, seg = tid & 15;
            const float* p = Wbase + (size_t)(k0 + r) * (2 * IDIM) + n0 + seg * 4;
            *(float4*)&sW1[r][seg * 4] = *(const float4*)p;
            *(float4*)&sW3[r][seg * 4] = *(const float4*)(p + IDIM);
        }
        __syncthreads();

#pragma unroll
        for (int kk = 0; kk < KC; kk += 8) {
            wmma::fragment<wmma::matrix_a, 16, 16, 8, wmma::precision::tf32, wmma::row_major> a[2];
            wmma::fragment<wmma::matrix_b, 16, 16, 8, wmma::precision::tf32, wmma::row_major> bg[2], bu[2];
#pragma unroll
            for (int i = 0; i < 2; i++) {
                wmma::load_matrix_sync(a[i], &sX[wm * 32 + i * 16][kk], PADX);
#pragma unroll
                for (int x = 0; x < a[i].num_elements; x++)
                    a[i].x[x] = wmma::__float_to_tf32(a[i].x[x]);
            }
#pragma unroll
            for (int j = 0; j < 2; j++) {
                wmma::load_matrix_sync(bg[j], &sW1[kk][wn * 32 + j * 16], PADW);
                wmma::load_matrix_sync(bu[j], &sW3[kk][wn * 32 + j * 16], PADW);
#pragma unroll
                for (int x = 0; x < bg[j].num_elements; x++) {
                    bg[j].x[x] = wmma::__float_to_tf32(bg[j].x[x]);
                    bu[j].x[x] = wmma::__float_to_tf32(bu[j].x[x]);
                }
            }
#pragma unroll
            for (int i = 0; i < 2; i++)
#pragma unroll
                for (int j = 0; j < 2; j++) {
                    wmma::mma_sync(accg[i][j], a[i], bg[j], accg[i][j]);
                    wmma::mma_sync(accu[i][j], a[i], bu[j], accu[i][j]);
                }
        }
        __syncthreads();
    }

    // epilogue: act = silu(gate) * up, computed in-fragment (identical layouts)
#pragma unroll
    for (int i = 0; i < 2; i++)
#pragma unroll
        for (int j = 0; j < 2; j++) {
#pragma unroll
            for (int x = 0; x < accg[i][j].num_elements; x++) {
                float g = accg[i][j].x[x];
                float u = accu[i][j].x[x];
                accg[i][j].x[x] = (g / (1.f + expf(-g))) * u;
            }
            wmma::store_matrix_sync(&stag[warp][0][0], accg[i][j], PADS, wmma::mem_row_major);
            __syncwarp();
            int r0 = wm * 32 + i * 16;
            int c0 = n0 + wn * 32 + j * 16;
#pragma unroll
            for (int q = 0; q < 8; q++) {
                int idx = q * 32 + lane;
                int rr = idx >> 4, cc = idx & 15;
                int gr = m0 + r0 + rr;
                if (gr < m_end)
                    g_act[(size_t)gr * IDIM + c0 + cc] = stag[warp][rr][cc];
            }
            __syncwarp();
        }
}

// ---------------- GEMM2: out[tok] += w * (A[slot] @ W2[e]) ----------------
// grid: (H/64=32, 32 m-tiles max, E)
__global__ __launch_bounds__(256) void k_gemm2(const float* __restrict__ W2,
                                               float* __restrict__ out) {
    int e = blockIdx.z;
    int m_beg = g_off[e], m_end = g_off[e + 1];
    int m0 = m_beg + blockIdx.y * TM;
    if (m0 >= m_end) return;
    int n0 = blockIdx.x * TN;   // column within [0, H)

    __shared__ float sA[TM][PADX];
    __shared__ float sW[KC][PADW];
    __shared__ float stag[8][16][PADS];
    __shared__ int   stok[TM];
    __shared__ float swt[TM];

    int tid = threadIdx.x, warp = tid >> 5, lane = tid & 31;
    int wm = warp >> 1;
    int wn = warp & 1;

    if (tid < TM) {
        int gr = m0 + tid;
        bool v = (gr < m_end);
        stok[tid] = v ? g_slot_tok[gr] : -1;
        swt[tid]  = v ? g_slot_w[gr]   : 0.f;
    }
    __syncthreads();

    wmma::fragment<wmma::accumulator, 16, 16, 8, float> acc[2][2];
#pragma unroll
    for (int i = 0; i < 2; i++)
#pragma unroll
        for (int j = 0; j < 2; j++)
            wmma::fill_fragment(acc[i][j], 0.f);

    const float* Wbase = W2 + (size_t)e * IDIM * HDIM;

    for (int k0 = 0; k0 < IDIM; k0 += KC) {
        // A tile (contiguous slots, no gather)
#pragma unroll
        for (int it = 0; it < 2; it++) {
            int f = tid + it * 256;
            int r = f >> 2, seg = f & 3;
            int gr = m0 + r;
            float4 v = make_float4(0.f, 0.f, 0.f, 0.f);
            if (gr < m_end) v = *(const float4*)&g_act[(size_t)gr * IDIM + k0 + seg * 4];
            *(float4*)&sA[r][seg * 4] = v;
        }
        // W2 tile: 16 x 64 -> 256 float4, 1 per thread
        {
            int r = tid >> 4, seg = tid & 15;
            *(float4*)&sW[r][seg * 4] =
                *(const float4*)&Wbase[(size_t)(k0 + r) * HDIM + n0 + seg * 4];
        }
        __syncthreads();

#pragma unroll
        for (int kk = 0; kk < KC; kk += 8) {
            wmma::fragment<wmma::matrix_a, 16, 16, 8, wmma::precision::tf32, wmma::row_major> a[2];
            wmma::fragment<wmma::matrix_b, 16, 16, 8, wmma::precision::tf32, wmma::row_major> b[2];
#pragma unroll
            for (int i = 0; i < 2; i++) {
                wmma::load_matrix_sync(a[i], &sA[wm * 32 + i * 16][kk], PADX);
#pragma unroll
                for (int x = 0; x < a[i].num_elements; x++)
                    a[i].x[x] = wmma::__float_to_tf32(a[i].x[x]);
            }
#pragma unroll
            for (int j = 0; j < 2; j++) {
                wmma::load_matrix_sync(b[j], &sW[kk][wn * 32 + j * 16], PADW);
#pragma unroll
                for (int x = 0; x < b[j].num_elements; x++)
                    b[j].x[x] = wmma::__float_to_tf32(b[j].x[x]);
            }
#pragma unroll
            for (int i = 0; i < 2; i++)
#pragma unroll
                for (int j = 0; j < 2; j++)
                    wmma::mma_sync(acc[i][j], a[i], b[j], acc[i][j]);
        }
        __syncthreads();
    }

    // epilogue: weighted atomic scatter into out[tok, :]
#pragma unroll
    for (int i = 0; i < 2; i++)
#pragma unroll
        for (int j = 0; j < 2; j++) {
            wmma::store_matrix_sync(&stag[warp][0][0], acc[i][j], PADS, wmma::mem_row_major);
            __syncwarp();
            int r0 = wm * 32 + i * 16;
            int c0 = n0 + wn * 32 + j * 16;
#pragma unroll
            for (int q = 0; q < 8; q++) {
                int idx = q * 32 + lane;
                int rr = idx >> 4, cc = idx & 15;
                int gr = m0 + r0 + rr;
                if (gr < m_end) {
                    int tok = stok[r0 + rr];
                    float v = stag[warp][rr][cc] * swt[r0 + rr];
                    atomicAdd(&out[(size_t)tok * HDIM + c0 + cc], v);
                }
            }
            __syncwarp();
        }
}

// ---------------- launch ----------------
extern "C" void kernel_launch(void* const* d_in, const int* in_sizes, int n_in,
                              void* d_out, int out_size) {
    const float* X      = (const float*)d_in[0];
    const float* logits = (const float*)d_in[1];
    const float* W13    = (const float*)d_in[2];
    const float* W2     = (const float*)d_in[3];
    float* out = (float*)d_out;

    int n_out = T_TOK * HDIM;
    k_init<<<(n_out + 1023) / 1024, 1024>>>(out, n_out);
    k_route<<<(T_TOK + 255) / 256, 256>>>(logits);
    k_scan<<<1, 1>>>();
    k_scatter<<<(T_TOK + 255) / 256, 256>>>();

    dim3 g1(IDIM / TN, (T_TOK + TM - 1) / TM, NE);   // (64, 32, 8)
    k_gemm1<<<g1, 256>>>(X, W13);

    dim3 g2(HDIM / TN, (T_TOK + TM - 1) / TM, NE);   // (32, 32, 8)
    k_gemm2<<<g2, 256>>>(W2, out);
}